// round 12
// baseline (speedup 1.0000x reference)
#include <cuda_runtime.h>
#include <math.h>
#include <stdint.h>

static constexpr int B  = 4;
static constexpr int S  = 1024;
static constexpr int D  = 1024;
static constexpr int H  = 16;
static constexpr int HD = 64;
static constexpr int M  = 4096;
static constexpr int E  = 1024;
static constexpr int BS = B * S;
static constexpr float EPS = 1e-6f;

// ---------------- scratch (no allocations allowed -> device globals) -------
__device__ float g_xn    [(size_t)BS * D];          // 16 MB (reused for xn2)
__device__ float g_qkv   [(size_t)BS * 3 * D];      // 48 MB
__device__ float g_ao    [(size_t)BS * D];          // 16 MB
__device__ float g_xmid  [(size_t)BS * D];          // 16 MB
__device__ float g_h     [(size_t)BS * 2 * M];      // 128 MB
__device__ float g_act   [(size_t)BS * M];          // 64 MB
__device__ float g_wt    [(size_t)16 * 1024 * 1024]; // 64 MB: tf32-rounded weights
__device__ float g_ss1   [B * 2 * D];
__device__ float g_ss2   [B * 2 * D];
__device__ float g_gates [B * 2 * D];

// ---------------- helpers ---------------------------------------------------
__device__ __forceinline__ uint32_t f2tf(float f) {
    uint32_t u;
    asm("cvt.rna.tf32.f32 %0, %1;" : "=r"(u) : "f"(f));
    return u;
}
__device__ __forceinline__ float rtf(float f) { return __uint_as_float(f2tf(f)); }

__device__ __forceinline__ void mma_tf32(float* d, const uint32_t* a, const uint32_t* b) {
    asm volatile(
        "mma.sync.aligned.m16n8k8.row.col.f32.tf32.tf32.f32 "
        "{%0,%1,%2,%3}, {%4,%5,%6,%7}, {%8,%9}, {%0,%1,%2,%3};\n"
        : "+f"(d[0]), "+f"(d[1]), "+f"(d[2]), "+f"(d[3])
        : "r"(a[0]), "r"(a[1]), "r"(a[2]), "r"(a[3]),
          "r"(b[0]), "r"(b[1]));
}

__device__ __forceinline__ void cp16(void* smem, const void* gmem) {
    uint32_t s = (uint32_t)__cvta_generic_to_shared(smem);
    asm volatile("cp.async.cg.shared.global [%0], [%1], 16;\n" :: "r"(s), "l"(gmem));
}

// ---------------- weight pre-round to tf32 ----------------------------------
__global__ void cvtw_kernel(const float4* __restrict__ src, float4* __restrict__ dst, int n4)
{
    const int i = blockIdx.x * 256 + threadIdx.x;
    if (i >= n4) return;
    const float4 v = src[i];
    float4 o;
    o.x = rtf(v.x); o.y = rtf(v.y); o.z = rtf(v.z); o.w = rtf(v.w);
    dst[i] = o;
}

// ---------------- tiny emb GEMMs: out[b,n] = emb[b,:] @ W[:,n] + bias[n] ----
__global__ void emb_gemm3_kernel(const float* __restrict__ emb,
                                 const float* __restrict__ W0, const float* __restrict__ b0, float* __restrict__ o0,
                                 const float* __restrict__ W1, const float* __restrict__ b1, float* __restrict__ o1,
                                 const float* __restrict__ W2, const float* __restrict__ b2, float* __restrict__ o2)
{
    const float* W; const float* bias; float* out;
    if (blockIdx.z == 0)      { W = W0; bias = b0; out = o0; }
    else if (blockIdx.z == 1) { W = W1; bias = b1; out = o1; }
    else                      { W = W2; bias = b2; out = o2; }
    const int b  = blockIdx.y;
    const int nl = threadIdx.x & 63;
    const int n  = blockIdx.x * 64 + nl;
    const int ks = threadIdx.x >> 6;          // 4-way K split
    const float* er = emb + b * E;
    float acc = 0.f;
    #pragma unroll 4
    for (int k = ks * 256; k < ks * 256 + 256; k++)
        acc += er[k] * W[(size_t)k * (2 * D) + n];
    __shared__ float red[256];
    red[threadIdx.x] = acc;
    __syncthreads();
    if (ks == 0)
        out[b * 2 * D + n] = red[nl] + red[nl + 64] + red[nl + 128] + red[nl + 192] + bias[n];
}

// ---------------- adaLN modulate: out = rmsnorm(x)*w*(1+ss[:D]) + ss[D:] ----
// output is tf32-rounded (feeds the tensor-core GEMMs)
__global__ void adaln_kernel(const float* __restrict__ x, const float* __restrict__ ss,
                             const float* __restrict__ w, float* __restrict__ out)
{
    const int r = blockIdx.x;
    const int b = r / S;
    const int t = threadIdx.x;
    const float4 v = *(const float4*)(x + (size_t)r * D + t * 4);
    float local = v.x * v.x + v.y * v.y + v.z * v.z + v.w * v.w;
    #pragma unroll
    for (int off = 16; off > 0; off >>= 1)
        local += __shfl_xor_sync(0xffffffffu, local, off);
    __shared__ float red[8];
    __shared__ float s_inv;
    if ((t & 31) == 0) red[t >> 5] = local;
    __syncthreads();
    if (t == 0) {
        float tot = 0.f;
        #pragma unroll
        for (int i = 0; i < 8; i++) tot += red[i];
        s_inv = 1.0f / (sqrtf(tot) * (1.0f / 32.0f) + EPS);   // /sqrt(D)
    }
    __syncthreads();
    const float inv = s_inv;
    const int j = t * 4;
    const float4 wv = *(const float4*)(w + j);
    const float4 sc = *(const float4*)(ss + b * 2 * D + j);
    const float4 sh = *(const float4*)(ss + b * 2 * D + D + j);
    float4 o;
    o.x = rtf(v.x * inv * wv.x * (1.f + sc.x) + sh.x);
    o.y = rtf(v.y * inv * wv.y * (1.f + sc.y) + sh.y);
    o.z = rtf(v.z * inv * wv.z * (1.f + sc.z) + sh.z);
    o.w = rtf(v.w * inv * wv.w * (1.f + sc.w) + sh.w);
    *(float4*)(out + (size_t)r * D + j) = o;
}

// ---------------- pipelined TF32 GEMM (cp.async double buffer) ---------------
// Operands MUST already be tf32-rounded in gmem (A by producers, B by cvtw).
// C[M x N] = A[M x K] @ B[K x N] (+ epilogue)
// EPI 0: C = AB + bias
// EPI 1: C = res + gate[row>>10, col] * (AB + bias)
template<int EPI>
__global__ void __launch_bounds__(256, 2) gemm2(
    const float* __restrict__ A, const float* __restrict__ Bw,
    const float* __restrict__ bias, float* __restrict__ C,
    const int Kdim, const int lda, const int ldb, const int ldc,
    const float* __restrict__ res, const float* __restrict__ gate)
{
    constexpr int KC   = 16;
    constexpr int ASTR = 20;    // A frag bank = (4g + tg + kb) % 32 : conflict-free
    constexpr int BSTR = 136;   // B frag bank = (8tg + g + ...) % 32: conflict-free
    __shared__ uint32_t As[2][128][ASTR];
    __shared__ uint32_t Bs[2][KC][BSTR];

    const int tid  = threadIdx.x;
    const int wid  = tid >> 5, lane = tid & 31;
    const int g    = lane >> 2, tg = lane & 3;
    const int wr   = wid & 3;       // 4 warps along M (32 rows each)
    const int wc   = wid >> 2;      // 2 warps along N (64 cols each)
    const int bm   = blockIdx.y * 128;
    const int bn   = blockIdx.x * 128;
    const float* Ab = A + (size_t)bm * lda;
    const float* Bb = Bw + bn;

    float acc[2][8][4] = {};

    auto load_tile = [&](int k0, int buf) {
        #pragma unroll
        for (int it = 0; it < 2; it++) {
            const int idx = tid + it * 256;
            const int m = idx >> 2, kq = (idx & 3) * 4;
            cp16(&As[buf][m][kq], Ab + (size_t)m * lda + k0 + kq);
        }
        #pragma unroll
        for (int it = 0; it < 2; it++) {
            const int idx = tid + it * 256;
            const int kr = idx >> 5, nq = (idx & 31) * 4;
            cp16(&Bs[buf][kr][nq], Bb + (size_t)(k0 + kr) * ldb + nq);
        }
        asm volatile("cp.async.commit_group;\n");
    };

    load_tile(0, 0);
    int buf = 0;
    for (int k0 = 0; k0 < Kdim; k0 += KC) {
        if (k0 + KC < Kdim) {
            load_tile(k0 + KC, buf ^ 1);
            asm volatile("cp.async.wait_group 1;\n");
        } else {
            asm volatile("cp.async.wait_group 0;\n");
        }
        __syncthreads();
        #pragma unroll
        for (int kb = 0; kb < KC; kb += 8) {
            uint32_t af[2][4], bf[8][2];
            #pragma unroll
            for (int i = 0; i < 2; i++) {
                const int r = wr * 32 + i * 16 + g;
                af[i][0] = As[buf][r    ][kb + tg];
                af[i][1] = As[buf][r + 8][kb + tg];
                af[i][2] = As[buf][r    ][kb + tg + 4];
                af[i][3] = As[buf][r + 8][kb + tg + 4];
            }
            #pragma unroll
            for (int j = 0; j < 8; j++) {
                const int c = wc * 64 + j * 8 + g;
                bf[j][0] = Bs[buf][kb + tg    ][c];
                bf[j][1] = Bs[buf][kb + tg + 4][c];
            }
            #pragma unroll
            for (int i = 0; i < 2; i++)
                #pragma unroll
                for (int j = 0; j < 8; j++)
                    mma_tf32(acc[i][j], af[i], bf[j]);
        }
        __syncthreads();
        buf ^= 1;
    }

    // epilogue
    #pragma unroll
    for (int i = 0; i < 2; i++) {
        const int r0 = bm + wr * 32 + i * 16 + g;
        #pragma unroll
        for (int h2 = 0; h2 < 2; h2++) {
            const int r = r0 + h2 * 8;
            float* crow = C + (size_t)r * ldc;
            #pragma unroll
            for (int j = 0; j < 8; j++) {
                const int col = bn + wc * 64 + j * 8 + tg * 2;
                const float v0 = acc[i][j][h2 * 2 + 0];
                const float v1 = acc[i][j][h2 * 2 + 1];
                float2 o;
                if (EPI == 0) {
                    o.x = v0 + bias[col];
                    o.y = v1 + bias[col + 1];
                } else {
                    const float* rrow = res + (size_t)r * ldc;
                    const float* grow = gate + (r >> 10) * (2 * D);
                    o.x = rrow[col]     + grow[col]     * (v0 + bias[col]);
                    o.y = rrow[col + 1] + grow[col + 1] * (v1 + bias[col + 1]);
                }
                *(float2*)(crow + col) = o;
            }
        }
    }
}

// ---------------- RoPE + per-head RMSNorm on q,k (warp per vector) ----------
// output tf32-rounded (feeds flash attention Q/K)
__global__ void rope_rms_kernel(float* __restrict__ qkv,
                                const float* __restrict__ nq_w,
                                const float* __restrict__ nk_w)
{
    const int vid  = blockIdx.x * 4 + (threadIdx.x >> 5);  // ((b*S+s)*2 + t)*H + h
    const int lane = threadIdx.x & 31;
    const int h  = vid & (H - 1);
    const int t  = (vid >> 4) & 1;       // 0 = q, 1 = k
    const int bs = vid >> 5;
    const int s  = bs & (S - 1);
    float* p = qkv + ((size_t)bs * 3 + t) * D + h * HD;
    const float x1 = p[lane];
    const float x2 = p[lane + 32];
    const float inv = exp2f(-(float)lane * (13.287712379549449f / 32.0f));
    float sn, cs;
    sincosf((float)s * inv, &sn, &cs);
    const float o1 = x1 * cs - x2 * sn;
    const float o2 = x2 * cs + x1 * sn;
    float ssum = o1 * o1 + o2 * o2;
    #pragma unroll
    for (int off = 16; off > 0; off >>= 1)
        ssum += __shfl_xor_sync(0xffffffffu, ssum, off);
    const float invn = 1.0f / (sqrtf(ssum) * 0.125f + EPS);   // /sqrt(64)
    const float* w = t ? nk_w : nq_w;
    p[lane]      = rtf(o1 * invn * w[lane]);
    p[lane + 32] = rtf(o2 * invn * w[lane + 32]);
}

// ---------------- fused flash attention --------------------------------------
// grid (S/128, B*H), 256 threads. Q tile 128 rows in regs, KV tiles of 64.
__global__ void flash_kernel(const float* __restrict__ qkv, float* __restrict__ ao)
{
    __shared__ uint32_t Ks[64][68];   // K[kv][d] raw layout; frag bank = lane
    __shared__ uint32_t Vs[64][72];   // V[kv][d] raw layout; frag bank = 8tg+g
    const int tid  = threadIdx.x;
    const int wid  = tid >> 5, lane = tid & 31;
    const int g    = lane >> 2, tg = lane & 3;
    const int bh = blockIdx.y, b = bh >> 4, h = bh & 15;
    const int q0 = blockIdx.x * 128;

    const float* Qg = qkv + ((size_t)(b * S + q0) * 3) * D + h * HD;

    // --- load Q fragments (scale 1/8 folded, tf32) via smem staging ---------
    uint32_t qf[8][4];
    #pragma unroll
    for (int half = 0; half < 2; half++) {
        #pragma unroll
        for (int it = 0; it < 4; it++) {
            const int idx = tid + it * 256;
            const int r = idx >> 4, c4 = (idx & 15) * 4;
            const float4 v = *(const float4*)(Qg + (size_t)(half * 64 + r) * (3 * D) + c4);
            uint4 u;
            u.x = f2tf(v.x * 0.125f); u.y = f2tf(v.y * 0.125f);
            u.z = f2tf(v.z * 0.125f); u.w = f2tf(v.w * 0.125f);
            *(uint4*)&Ks[r][c4] = u;
        }
        __syncthreads();
        if ((wid >> 2) == half) {
            const int r0 = (wid & 3) * 16 + g;
            #pragma unroll
            for (int kb = 0; kb < 8; kb++) {
                qf[kb][0] = Ks[r0    ][kb * 8 + tg];
                qf[kb][1] = Ks[r0 + 8][kb * 8 + tg];
                qf[kb][2] = Ks[r0    ][kb * 8 + tg + 4];
                qf[kb][3] = Ks[r0 + 8][kb * 8 + tg + 4];
            }
        }
        __syncthreads();
    }

    float m0 = -1e30f, m1 = -1e30f, l0 = 0.f, l1 = 0.f;
    float o[8][4] = {};

    const float* Kg0 = qkv + ((size_t)(b * S) * 3 + 1) * D + h * HD;
    const float* Vg0 = qkv + ((size_t)(b * S) * 3 + 2) * D + h * HD;

    const int  src0 = (lane & ~3) | (tg >> 1);
    const int  src2 = src0 + 2;
    const bool odd  = tg & 1;

    for (int t = 0; t < 16; t++) {
        const int kv0 = t * 64;
        // load K,V tile (tf32-convert V; K already rounded but re-round is free)
        #pragma unroll
        for (int it = 0; it < 4; it++) {
            const int idx = tid + it * 256;
            const int r = idx >> 4, c4 = (idx & 15) * 4;
            const size_t off = (size_t)(kv0 + r) * (3 * D) + c4;
            const float4 kvv = *(const float4*)(Kg0 + off);
            const float4 vv  = *(const float4*)(Vg0 + off);
            uint4 u;
            u.x = f2tf(kvv.x); u.y = f2tf(kvv.y); u.z = f2tf(kvv.z); u.w = f2tf(kvv.w);
            *(uint4*)&Ks[r][c4] = u;
            uint4 w;
            w.x = f2tf(vv.x); w.y = f2tf(vv.y); w.z = f2tf(vv.z); w.w = f2tf(vv.w);
            *(uint4*)&Vs[r][c4] = w;
        }
        __syncthreads();

        // S = Q @ K^T   (per warp: 16 q rows x 64 kv cols)
        float sacc[8][4] = {};
        #pragma unroll
        for (int kb = 0; kb < 8; kb++) {
            #pragma unroll
            for (int j = 0; j < 8; j++) {
                uint32_t bf[2];
                bf[0] = Ks[j * 8 + g][kb * 8 + tg];
                bf[1] = Ks[j * 8 + g][kb * 8 + tg + 4];
                mma_tf32(sacc[j], qf[kb], bf);
            }
        }

        // online softmax (rows g and g+8; quad holds a full row)
        float mx0 = -1e30f, mx1 = -1e30f;
        #pragma unroll
        for (int j = 0; j < 8; j++) {
            mx0 = fmaxf(mx0, fmaxf(sacc[j][0], sacc[j][1]));
            mx1 = fmaxf(mx1, fmaxf(sacc[j][2], sacc[j][3]));
        }
        mx0 = fmaxf(mx0, __shfl_xor_sync(0xffffffffu, mx0, 1));
        mx0 = fmaxf(mx0, __shfl_xor_sync(0xffffffffu, mx0, 2));
        mx1 = fmaxf(mx1, __shfl_xor_sync(0xffffffffu, mx1, 1));
        mx1 = fmaxf(mx1, __shfl_xor_sync(0xffffffffu, mx1, 2));
        const float mn0 = fmaxf(m0, mx0), mn1 = fmaxf(m1, mx1);
        const float a0 = __expf(m0 - mn0), a1 = __expf(m1 - mn1);
        m0 = mn0; m1 = mn1;
        l0 *= a0; l1 *= a1;
        #pragma unroll
        for (int j = 0; j < 8; j++) {
            sacc[j][0] = __expf(sacc[j][0] - m0);
            sacc[j][1] = __expf(sacc[j][1] - m0);
            sacc[j][2] = __expf(sacc[j][2] - m1);
            sacc[j][3] = __expf(sacc[j][3] - m1);
            l0 += sacc[j][0] + sacc[j][1];
            l1 += sacc[j][2] + sacc[j][3];
        }
        #pragma unroll
        for (int jn = 0; jn < 8; jn++) {
            o[jn][0] *= a0; o[jn][1] *= a0;
            o[jn][2] *= a1; o[jn][3] *= a1;
        }

        // O += P @ V : rebuild A-fragments of P with quad shuffles
        #pragma unroll
        for (int kk = 0; kk < 8; kk++) {
            const float v00 = __shfl_sync(0xffffffffu, sacc[kk][0], src0);
            const float v01 = __shfl_sync(0xffffffffu, sacc[kk][1], src0);
            const float v20 = __shfl_sync(0xffffffffu, sacc[kk][0], src2);
            const float v21 = __shfl_sync(0xffffffffu, sacc[kk][1], src2);
            const float v10 = __shfl_sync(0xffffffffu, sacc[kk][2], src0);
            const float v11 = __shfl_sync(0xffffffffu, sacc[kk][3], src0);
            const float v30 = __shfl_sync(0xffffffffu, sacc[kk][2], src2);
            const float v31 = __shfl_sync(0xffffffffu, sacc[kk][3], src2);
            uint32_t af[4];
            af[0] = f2tf(odd ? v01 : v00);   // P[g   ][8kk+tg]
            af[1] = f2tf(odd ? v11 : v10);   // P[g+8 ][8kk+tg]
            af[2] = f2tf(odd ? v21 : v20);   // P[g   ][8kk+tg+4]
            af[3] = f2tf(odd ? v31 : v30);   // P[g+8 ][8kk+tg+4]
            #pragma unroll
            for (int jn = 0; jn < 8; jn++) {
                uint32_t bf[2];
                bf[0] = Vs[kk * 8 + tg    ][jn * 8 + g];
                bf[1] = Vs[kk * 8 + tg + 4][jn * 8 + g];
                mma_tf32(o[jn], af, bf);
            }
        }
        __syncthreads();
    }

    // finalize: 1/l and store (tf32-rounded; ao feeds proj GEMM)
    l0 += __shfl_xor_sync(0xffffffffu, l0, 1);
    l0 += __shfl_xor_sync(0xffffffffu, l0, 2);
    l1 += __shfl_xor_sync(0xffffffffu, l1, 1);
    l1 += __shfl_xor_sync(0xffffffffu, l1, 2);
    const float i0 = 1.f / l0, i1 = 1.f / l1;
    const int r0 = q0 + wid * 16 + g;
    #pragma unroll
    for (int jn = 0; jn < 8; jn++) {
        const int c = h * HD + jn * 8 + tg * 2;
        float2 w0, w1;
        w0.x = rtf(o[jn][0] * i0);
        w0.y = rtf(o[jn][1] * i0);
        w1.x = rtf(o[jn][2] * i1);
        w1.y = rtf(o[jn][3] * i1);
        *(float2*)(ao + (size_t)(b * S + r0    ) * D + c) = w0;
        *(float2*)(ao + (size_t)(b * S + r0 + 8) * D + c) = w1;
    }
}

// ---------------- SwiGLU: act = h[:, :M] * silu(h[:, M:]) --------------------
// output tf32-rounded (feeds out GEMM)
__global__ void silu_kernel(const float* __restrict__ hb, float* __restrict__ act)
{
    const size_t idx = (size_t)blockIdx.x * 256 + threadIdx.x;   // float4 units
    const size_t r = idx >> 10;              // M/4 = 1024 float4 per row
    const int    j = (int)((idx & 1023) << 2);
    const float4 a = *(const float4*)(hb + r * (2 * M) + j);
    const float4 z = *(const float4*)(hb + r * (2 * M) + M + j);
    float4 o;
    o.x = rtf(a.x * z.x / (1.f + __expf(-z.x)));
    o.y = rtf(a.y * z.y / (1.f + __expf(-z.y)));
    o.z = rtf(a.z * z.z / (1.f + __expf(-z.z)));
    o.w = rtf(a.w * z.w / (1.f + __expf(-z.w)));
    *(float4*)(act + r * M + j) = o;
}

// ---------------- launch ------------------------------------------------------
extern "C" void kernel_launch(void* const* d_in, const int* in_sizes, int n_in,
                              void* d_out, int out_size)
{
    const float* x       = (const float*)d_in[0];
    const float* emb     = (const float*)d_in[1];
    const float* ln1_w   = (const float*)d_in[2];
    const float* ln1_lW  = (const float*)d_in[3];
    const float* ln1_lb  = (const float*)d_in[4];
    const float* ln2_w   = (const float*)d_in[5];
    const float* ln2_lW  = (const float*)d_in[6];
    const float* ln2_lb  = (const float*)d_in[7];
    const float* qkv_W   = (const float*)d_in[8];
    const float* qkv_b   = (const float*)d_in[9];
    const float* proj_W  = (const float*)d_in[10];
    const float* proj_b  = (const float*)d_in[11];
    const float* nq_w    = (const float*)d_in[12];
    const float* nk_w    = (const float*)d_in[13];
    const float* mlp_W   = (const float*)d_in[14];
    const float* mlp_b   = (const float*)d_in[15];
    const float* out_W   = (const float*)d_in[16];
    const float* out_b   = (const float*)d_in[17];
    const float* gates_W = (const float*)d_in[18];
    const float* gates_b = (const float*)d_in[19];
    float* outp = (float*)d_out;

    float *xn, *qkv, *ao, *xmid, *hb, *act, *wt, *ss1, *ss2, *gates;
    cudaGetSymbolAddress((void**)&xn,    g_xn);
    cudaGetSymbolAddress((void**)&qkv,   g_qkv);
    cudaGetSymbolAddress((void**)&ao,    g_ao);
    cudaGetSymbolAddress((void**)&xmid,  g_xmid);
    cudaGetSymbolAddress((void**)&hb,    g_h);
    cudaGetSymbolAddress((void**)&act,   g_act);
    cudaGetSymbolAddress((void**)&wt,    g_wt);
    cudaGetSymbolAddress((void**)&ss1,   g_ss1);
    cudaGetSymbolAddress((void**)&ss2,   g_ss2);
    cudaGetSymbolAddress((void**)&gates, g_gates);

    // tf32-rounded weight copies (carved from g_wt)
    float* wq = wt;                               // 1024*3072
    float* wp = wq + (size_t)D * 3 * D;           // 1024*1024
    float* wm = wp + (size_t)D * D;               // 1024*8192
    float* wo = wm + (size_t)D * 2 * M;           // 4096*1024

    cvtw_kernel<<<(D * 3 * D / 4 + 255) / 256, 256>>>((const float4*)qkv_W,  (float4*)wq, D * 3 * D / 4);
    cvtw_kernel<<<(D * D / 4     + 255) / 256, 256>>>((const float4*)proj_W, (float4*)wp, D * D / 4);
    cvtw_kernel<<<(D * 2 * M / 4 + 255) / 256, 256>>>((const float4*)mlp_W,  (float4*)wm, D * 2 * M / 4);
    cvtw_kernel<<<(M * D / 4     + 255) / 256, 256>>>((const float4*)out_W,  (float4*)wo, M * D / 4);

    // gates / ss1 / ss2 (all emb @ [E, 2D] + bias)
    emb_gemm3_kernel<<<dim3(2 * D / 64, B, 3), 256>>>(emb,
        gates_W, gates_b, gates,
        ln1_lW,  ln1_lb,  ss1,
        ln2_lW,  ln2_lb,  ss2);

    // xn = adaLN(x, ss1)   (tf32-rounded)
    adaln_kernel<<<BS, 256>>>(x, ss1, ln1_w, xn);

    // qkv = xn @ qkv_W + qkv_b
    gemm2<0><<<dim3(3 * D / 128, BS / 128), 256>>>(
        xn, wq, qkv_b, qkv, D, D, 3 * D, 3 * D, nullptr, nullptr);

    // rope + head rmsnorm on q, k (in place, tf32-rounded)
    rope_rms_kernel<<<BS * 2 * H / 4, 128>>>(qkv, nq_w, nk_w);

    // fused attention -> ao (tf32-rounded)
    flash_kernel<<<dim3(S / 128, B * H), 256>>>(qkv, ao);

    // xmid = x + gate_mha * (ao @ proj_W + proj_b)
    gemm2<1><<<dim3(D / 128, BS / 128), 256>>>(
        ao, wp, proj_b, xmid, D, D, D, D, x, gates);

    // xn2 = adaLN(xmid, ss2)  (tf32-rounded)
    adaln_kernel<<<BS, 256>>>(xmid, ss2, ln2_w, xn);

    // h = xn2 @ mlp_W + mlp_b
    gemm2<0><<<dim3(2 * M / 128, BS / 128), 256>>>(
        xn, wm, mlp_b, hb, D, D, 2 * M, 2 * M, nullptr, nullptr);

    // act = h[:, :M] * silu(h[:, M:])  (tf32-rounded)
    silu_kernel<<<(int)((size_t)BS * M / 4 / 256), 256>>>(hb, act);

    // out = xmid + gate_mlp * (act @ out_W + out_b)
    gemm2<1><<<dim3(D / 128, BS / 128), 256>>>(
        act, wo, out_b, outp, M, M, D, D, xmid, gates + D);
}

// round 13
// speedup vs baseline: 1.0042x; 1.0042x over previous
#include <cuda_runtime.h>
#include <math.h>
#include <stdint.h>

static constexpr int B  = 4;
static constexpr int S  = 1024;
static constexpr int D  = 1024;
static constexpr int H  = 16;
static constexpr int HD = 64;
static constexpr int M  = 4096;
static constexpr int E  = 1024;
static constexpr int BS = B * S;
static constexpr float EPS = 1e-6f;

// ---------------- scratch (no allocations allowed -> device globals) -------
__device__ float g_xn    [(size_t)BS * D];          // 16 MB (reused for xn2)
__device__ float g_qkv   [(size_t)BS * 3 * D];      // 48 MB
__device__ float g_ao    [(size_t)BS * D];          // 16 MB
__device__ float g_xmid  [(size_t)BS * D];          // 16 MB
__device__ float g_h     [(size_t)BS * 2 * M];      // 128 MB
__device__ float g_act   [(size_t)BS * M];          // 64 MB
__device__ float g_wt    [(size_t)16 * 1024 * 1024]; // 64 MB: tf32-rounded weights
__device__ float g_ss1   [B * 2 * D];
__device__ float g_ss2   [B * 2 * D];
__device__ float g_gates [B * 2 * D];

// ---------------- helpers ---------------------------------------------------
__device__ __forceinline__ uint32_t f2tf(float f) {
    uint32_t u;
    asm("cvt.rna.tf32.f32 %0, %1;" : "=r"(u) : "f"(f));
    return u;
}
__device__ __forceinline__ float rtf(float f) { return __uint_as_float(f2tf(f)); }

__device__ __forceinline__ void mma_tf32(float* d, const uint32_t* a, const uint32_t* b) {
    asm volatile(
        "mma.sync.aligned.m16n8k8.row.col.f32.tf32.tf32.f32 "
        "{%0,%1,%2,%3}, {%4,%5,%6,%7}, {%8,%9}, {%0,%1,%2,%3};\n"
        : "+f"(d[0]), "+f"(d[1]), "+f"(d[2]), "+f"(d[3])
        : "r"(a[0]), "r"(a[1]), "r"(a[2]), "r"(a[3]),
          "r"(b[0]), "r"(b[1]));
}

__device__ __forceinline__ void cp16(void* smem, const void* gmem) {
    uint32_t s = (uint32_t)__cvta_generic_to_shared(smem);
    asm volatile("cp.async.cg.shared.global [%0], [%1], 16;\n" :: "r"(s), "l"(gmem));
}

// ---------------- weight pre-round to tf32 ----------------------------------
__global__ void cvtw_kernel(const float4* __restrict__ src, float4* __restrict__ dst, int n4)
{
    const int i = blockIdx.x * 256 + threadIdx.x;
    if (i >= n4) return;
    const float4 v = src[i];
    float4 o;
    o.x = rtf(v.x); o.y = rtf(v.y); o.z = rtf(v.z); o.w = rtf(v.w);
    dst[i] = o;
}

// ---------------- tiny emb GEMMs: out[b,n] = emb[b,:] @ W[:,n] + bias[n] ----
__global__ void emb_gemm3_kernel(const float* __restrict__ emb,
                                 const float* __restrict__ W0, const float* __restrict__ b0, float* __restrict__ o0,
                                 const float* __restrict__ W1, const float* __restrict__ b1, float* __restrict__ o1,
                                 const float* __restrict__ W2, const float* __restrict__ b2, float* __restrict__ o2)
{
    const float* W; const float* bias; float* out;
    if (blockIdx.z == 0)      { W = W0; bias = b0; out = o0; }
    else if (blockIdx.z == 1) { W = W1; bias = b1; out = o1; }
    else                      { W = W2; bias = b2; out = o2; }
    const int b  = blockIdx.y;
    const int nl = threadIdx.x & 63;
    const int n  = blockIdx.x * 64 + nl;
    const int ks = threadIdx.x >> 6;          // 4-way K split
    const float* er = emb + b * E;
    float acc = 0.f;
    #pragma unroll 4
    for (int k = ks * 256; k < ks * 256 + 256; k++)
        acc += er[k] * W[(size_t)k * (2 * D) + n];
    __shared__ float red[256];
    red[threadIdx.x] = acc;
    __syncthreads();
    if (ks == 0)
        out[b * 2 * D + n] = red[nl] + red[nl + 64] + red[nl + 128] + red[nl + 192] + bias[n];
}

// ---------------- adaLN modulate: out = rmsnorm(x)*w*(1+ss[:D]) + ss[D:] ----
// output is tf32-rounded (feeds the tensor-core GEMMs)
__global__ void adaln_kernel(const float* __restrict__ x, const float* __restrict__ ss,
                             const float* __restrict__ w, float* __restrict__ out)
{
    const int r = blockIdx.x;
    const int b = r / S;
    const int t = threadIdx.x;
    const float4 v = *(const float4*)(x + (size_t)r * D + t * 4);
    float local = v.x * v.x + v.y * v.y + v.z * v.z + v.w * v.w;
    #pragma unroll
    for (int off = 16; off > 0; off >>= 1)
        local += __shfl_xor_sync(0xffffffffu, local, off);
    __shared__ float red[8];
    __shared__ float s_inv;
    if ((t & 31) == 0) red[t >> 5] = local;
    __syncthreads();
    if (t == 0) {
        float tot = 0.f;
        #pragma unroll
        for (int i = 0; i < 8; i++) tot += red[i];
        s_inv = 1.0f / (sqrtf(tot) * (1.0f / 32.0f) + EPS);   // /sqrt(D)
    }
    __syncthreads();
    const float inv = s_inv;
    const int j = t * 4;
    const float4 wv = *(const float4*)(w + j);
    const float4 sc = *(const float4*)(ss + b * 2 * D + j);
    const float4 sh = *(const float4*)(ss + b * 2 * D + D + j);
    float4 o;
    o.x = rtf(v.x * inv * wv.x * (1.f + sc.x) + sh.x);
    o.y = rtf(v.y * inv * wv.y * (1.f + sc.y) + sh.y);
    o.z = rtf(v.z * inv * wv.z * (1.f + sc.z) + sh.z);
    o.w = rtf(v.w * inv * wv.w * (1.f + sc.w) + sh.w);
    *(float4*)(out + (size_t)r * D + j) = o;
}

// ---------------- pipelined TF32 GEMM (cp.async double buffer) ---------------
// Operands MUST already be tf32-rounded in gmem (A by producers, B by cvtw).
// C[M x N] = A[M x K] @ B[K x N] (+ epilogue)
// EPI 0: C = AB + bias
// EPI 1: C = res + gate[row>>10, col] * (AB + bias)
template<int EPI>
__global__ void __launch_bounds__(256, 2) gemm2(
    const float* __restrict__ A, const float* __restrict__ Bw,
    const float* __restrict__ bias, float* __restrict__ C,
    const int Kdim, const int lda, const int ldb, const int ldc,
    const float* __restrict__ res, const float* __restrict__ gate)
{
    constexpr int KC   = 16;
    constexpr int ASTR = 20;    // A frag bank = (4g + tg + kb) % 32 : conflict-free
    constexpr int BSTR = 136;   // B frag bank = (8tg + g + ...) % 32: conflict-free
    __shared__ uint32_t As[2][128][ASTR];
    __shared__ uint32_t Bs[2][KC][BSTR];

    const int tid  = threadIdx.x;
    const int wid  = tid >> 5, lane = tid & 31;
    const int g    = lane >> 2, tg = lane & 3;
    const int wr   = wid & 3;       // 4 warps along M (32 rows each)
    const int wc   = wid >> 2;      // 2 warps along N (64 cols each)
    const int bm   = blockIdx.y * 128;
    const int bn   = blockIdx.x * 128;
    const float* Ab = A + (size_t)bm * lda;
    const float* Bb = Bw + bn;

    float acc[2][8][4] = {};

    auto load_tile = [&](int k0, int buf) {
        #pragma unroll
        for (int it = 0; it < 2; it++) {
            const int idx = tid + it * 256;
            const int m = idx >> 2, kq = (idx & 3) * 4;
            cp16(&As[buf][m][kq], Ab + (size_t)m * lda + k0 + kq);
        }
        #pragma unroll
        for (int it = 0; it < 2; it++) {
            const int idx = tid + it * 256;
            const int kr = idx >> 5, nq = (idx & 31) * 4;
            cp16(&Bs[buf][kr][nq], Bb + (size_t)(k0 + kr) * ldb + nq);
        }
        asm volatile("cp.async.commit_group;\n");
    };

    load_tile(0, 0);
    int buf = 0;
    for (int k0 = 0; k0 < Kdim; k0 += KC) {
        if (k0 + KC < Kdim) {
            load_tile(k0 + KC, buf ^ 1);
            asm volatile("cp.async.wait_group 1;\n");
        } else {
            asm volatile("cp.async.wait_group 0;\n");
        }
        __syncthreads();
        #pragma unroll
        for (int kb = 0; kb < KC; kb += 8) {
            uint32_t af[2][4], bf[8][2];
            #pragma unroll
            for (int i = 0; i < 2; i++) {
                const int r = wr * 32 + i * 16 + g;
                af[i][0] = As[buf][r    ][kb + tg];
                af[i][1] = As[buf][r + 8][kb + tg];
                af[i][2] = As[buf][r    ][kb + tg + 4];
                af[i][3] = As[buf][r + 8][kb + tg + 4];
            }
            #pragma unroll
            for (int j = 0; j < 8; j++) {
                const int c = wc * 64 + j * 8 + g;
                bf[j][0] = Bs[buf][kb + tg    ][c];
                bf[j][1] = Bs[buf][kb + tg + 4][c];
            }
            #pragma unroll
            for (int i = 0; i < 2; i++)
                #pragma unroll
                for (int j = 0; j < 8; j++)
                    mma_tf32(acc[i][j], af[i], bf[j]);
        }
        __syncthreads();
        buf ^= 1;
    }

    // epilogue
    #pragma unroll
    for (int i = 0; i < 2; i++) {
        const int r0 = bm + wr * 32 + i * 16 + g;
        #pragma unroll
        for (int h2 = 0; h2 < 2; h2++) {
            const int r = r0 + h2 * 8;
            float* crow = C + (size_t)r * ldc;
            #pragma unroll
            for (int j = 0; j < 8; j++) {
                const int col = bn + wc * 64 + j * 8 + tg * 2;
                const float v0 = acc[i][j][h2 * 2 + 0];
                const float v1 = acc[i][j][h2 * 2 + 1];
                float2 o;
                if (EPI == 0) {
                    o.x = v0 + bias[col];
                    o.y = v1 + bias[col + 1];
                } else {
                    const float* rrow = res + (size_t)r * ldc;
                    const float* grow = gate + (r >> 10) * (2 * D);
                    o.x = rrow[col]     + grow[col]     * (v0 + bias[col]);
                    o.y = rrow[col + 1] + grow[col + 1] * (v1 + bias[col + 1]);
                }
                *(float2*)(crow + col) = o;
            }
        }
    }
}

// ---------------- RoPE + per-head RMSNorm on q,k (warp per vector) ----------
// output tf32-rounded (feeds flash attention Q/K)
__global__ void rope_rms_kernel(float* __restrict__ qkv,
                                const float* __restrict__ nq_w,
                                const float* __restrict__ nk_w)
{
    const int vid  = blockIdx.x * 4 + (threadIdx.x >> 5);  // ((b*S+s)*2 + t)*H + h
    const int lane = threadIdx.x & 31;
    const int h  = vid & (H - 1);
    const int t  = (vid >> 4) & 1;       // 0 = q, 1 = k
    const int bs = vid >> 5;
    const int s  = bs & (S - 1);
    float* p = qkv + ((size_t)bs * 3 + t) * D + h * HD;
    const float x1 = p[lane];
    const float x2 = p[lane + 32];
    const float inv = exp2f(-(float)lane * (13.287712379549449f / 32.0f));
    float sn, cs;
    sincosf((float)s * inv, &sn, &cs);
    const float o1 = x1 * cs - x2 * sn;
    const float o2 = x2 * cs + x1 * sn;
    float ssum = o1 * o1 + o2 * o2;
    #pragma unroll
    for (int off = 16; off > 0; off >>= 1)
        ssum += __shfl_xor_sync(0xffffffffu, ssum, off);
    const float invn = 1.0f / (sqrtf(ssum) * 0.125f + EPS);   // /sqrt(64)
    const float* w = t ? nk_w : nq_w;
    p[lane]      = rtf(o1 * invn * w[lane]);
    p[lane + 32] = rtf(o2 * invn * w[lane + 32]);
}

// ---------------- fused flash attention --------------------------------------
// grid (S/128, B*H), 256 threads. Q tile 128 rows in regs, KV tiles of 64.
__global__ void flash_kernel(const float* __restrict__ qkv, float* __restrict__ ao)
{
    __shared__ uint32_t Ks[64][68];   // K[kv][d] raw layout; frag bank = lane
    __shared__ uint32_t Vs[64][72];   // V[kv][d] raw layout; frag bank = 8tg+g
    const int tid  = threadIdx.x;
    const int wid  = tid >> 5, lane = tid & 31;
    const int g    = lane >> 2, tg = lane & 3;
    const int bh = blockIdx.y, b = bh >> 4, h = bh & 15;
    const int q0 = blockIdx.x * 128;

    const float* Qg = qkv + ((size_t)(b * S + q0) * 3) * D + h * HD;

    // --- load Q fragments (scale 1/8 folded, tf32) via smem staging ---------
    uint32_t qf[8][4];
    #pragma unroll
    for (int half = 0; half < 2; half++) {
        #pragma unroll
        for (int it = 0; it < 4; it++) {
            const int idx = tid + it * 256;
            const int r = idx >> 4, c4 = (idx & 15) * 4;
            const float4 v = *(const float4*)(Qg + (size_t)(half * 64 + r) * (3 * D) + c4);
            uint4 u;
            u.x = f2tf(v.x * 0.125f); u.y = f2tf(v.y * 0.125f);
            u.z = f2tf(v.z * 0.125f); u.w = f2tf(v.w * 0.125f);
            *(uint4*)&Ks[r][c4] = u;
        }
        __syncthreads();
        if ((wid >> 2) == half) {
            const int r0 = (wid & 3) * 16 + g;
            #pragma unroll
            for (int kb = 0; kb < 8; kb++) {
                qf[kb][0] = Ks[r0    ][kb * 8 + tg];
                qf[kb][1] = Ks[r0 + 8][kb * 8 + tg];
                qf[kb][2] = Ks[r0    ][kb * 8 + tg + 4];
                qf[kb][3] = Ks[r0 + 8][kb * 8 + tg + 4];
            }
        }
        __syncthreads();
    }

    float m0 = -1e30f, m1 = -1e30f, l0 = 0.f, l1 = 0.f;
    float o[8][4] = {};

    const float* Kg0 = qkv + ((size_t)(b * S) * 3 + 1) * D + h * HD;
    const float* Vg0 = qkv + ((size_t)(b * S) * 3 + 2) * D + h * HD;

    const int  src0 = (lane & ~3) | (tg >> 1);
    const int  src2 = src0 + 2;
    const bool odd  = tg & 1;

    for (int t = 0; t < 16; t++) {
        const int kv0 = t * 64;
        // load K,V tile (tf32-convert V; K already rounded but re-round is free)
        #pragma unroll
        for (int it = 0; it < 4; it++) {
            const int idx = tid + it * 256;
            const int r = idx >> 4, c4 = (idx & 15) * 4;
            const size_t off = (size_t)(kv0 + r) * (3 * D) + c4;
            const float4 kvv = *(const float4*)(Kg0 + off);
            const float4 vv  = *(const float4*)(Vg0 + off);
            uint4 u;
            u.x = f2tf(kvv.x); u.y = f2tf(kvv.y); u.z = f2tf(kvv.z); u.w = f2tf(kvv.w);
            *(uint4*)&Ks[r][c4] = u;
            uint4 w;
            w.x = f2tf(vv.x); w.y = f2tf(vv.y); w.z = f2tf(vv.z); w.w = f2tf(vv.w);
            *(uint4*)&Vs[r][c4] = w;
        }
        __syncthreads();

        // S = Q @ K^T   (per warp: 16 q rows x 64 kv cols)
        float sacc[8][4] = {};
        #pragma unroll
        for (int kb = 0; kb < 8; kb++) {
            #pragma unroll
            for (int j = 0; j < 8; j++) {
                uint32_t bf[2];
                bf[0] = Ks[j * 8 + g][kb * 8 + tg];
                bf[1] = Ks[j * 8 + g][kb * 8 + tg + 4];
                mma_tf32(sacc[j], qf[kb], bf);
            }
        }

        // online softmax (rows g and g+8; quad holds a full row)
        float mx0 = -1e30f, mx1 = -1e30f;
        #pragma unroll
        for (int j = 0; j < 8; j++) {
            mx0 = fmaxf(mx0, fmaxf(sacc[j][0], sacc[j][1]));
            mx1 = fmaxf(mx1, fmaxf(sacc[j][2], sacc[j][3]));
        }
        mx0 = fmaxf(mx0, __shfl_xor_sync(0xffffffffu, mx0, 1));
        mx0 = fmaxf(mx0, __shfl_xor_sync(0xffffffffu, mx0, 2));
        mx1 = fmaxf(mx1, __shfl_xor_sync(0xffffffffu, mx1, 1));
        mx1 = fmaxf(mx1, __shfl_xor_sync(0xffffffffu, mx1, 2));
        const float mn0 = fmaxf(m0, mx0), mn1 = fmaxf(m1, mx1);
        const float a0 = __expf(m0 - mn0), a1 = __expf(m1 - mn1);
        m0 = mn0; m1 = mn1;
        l0 *= a0; l1 *= a1;
        #pragma unroll
        for (int j = 0; j < 8; j++) {
            sacc[j][0] = __expf(sacc[j][0] - m0);
            sacc[j][1] = __expf(sacc[j][1] - m0);
            sacc[j][2] = __expf(sacc[j][2] - m1);
            sacc[j][3] = __expf(sacc[j][3] - m1);
            l0 += sacc[j][0] + sacc[j][1];
            l1 += sacc[j][2] + sacc[j][3];
        }
        #pragma unroll
        for (int jn = 0; jn < 8; jn++) {
            o[jn][0] *= a0; o[jn][1] *= a0;
            o[jn][2] *= a1; o[jn][3] *= a1;
        }

        // O += P @ V : rebuild A-fragments of P with quad shuffles
        #pragma unroll
        for (int kk = 0; kk < 8; kk++) {
            const float v00 = __shfl_sync(0xffffffffu, sacc[kk][0], src0);
            const float v01 = __shfl_sync(0xffffffffu, sacc[kk][1], src0);
            const float v20 = __shfl_sync(0xffffffffu, sacc[kk][0], src2);
            const float v21 = __shfl_sync(0xffffffffu, sacc[kk][1], src2);
            const float v10 = __shfl_sync(0xffffffffu, sacc[kk][2], src0);
            const float v11 = __shfl_sync(0xffffffffu, sacc[kk][3], src0);
            const float v30 = __shfl_sync(0xffffffffu, sacc[kk][2], src2);
            const float v31 = __shfl_sync(0xffffffffu, sacc[kk][3], src2);
            uint32_t af[4];
            af[0] = f2tf(odd ? v01 : v00);   // P[g   ][8kk+tg]
            af[1] = f2tf(odd ? v11 : v10);   // P[g+8 ][8kk+tg]
            af[2] = f2tf(odd ? v21 : v20);   // P[g   ][8kk+tg+4]
            af[3] = f2tf(odd ? v31 : v30);   // P[g+8 ][8kk+tg+4]
            #pragma unroll
            for (int jn = 0; jn < 8; jn++) {
                uint32_t bf[2];
                bf[0] = Vs[kk * 8 + tg    ][jn * 8 + g];
                bf[1] = Vs[kk * 8 + tg + 4][jn * 8 + g];
                mma_tf32(o[jn], af, bf);
            }
        }
        __syncthreads();
    }

    // finalize: 1/l and store (tf32-rounded; ao feeds proj GEMM)
    l0 += __shfl_xor_sync(0xffffffffu, l0, 1);
    l0 += __shfl_xor_sync(0xffffffffu, l0, 2);
    l1 += __shfl_xor_sync(0xffffffffu, l1, 1);
    l1 += __shfl_xor_sync(0xffffffffu, l1, 2);
    const float i0 = 1.f / l0, i1 = 1.f / l1;
    const int r0 = q0 + wid * 16 + g;
    #pragma unroll
    for (int jn = 0; jn < 8; jn++) {
        const int c = h * HD + jn * 8 + tg * 2;
        float2 w0, w1;
        w0.x = rtf(o[jn][0] * i0);
        w0.y = rtf(o[jn][1] * i0);
        w1.x = rtf(o[jn][2] * i1);
        w1.y = rtf(o[jn][3] * i1);
        *(float2*)(ao + (size_t)(b * S + r0    ) * D + c) = w0;
        *(float2*)(ao + (size_t)(b * S + r0 + 8) * D + c) = w1;
    }
}

// ---------------- SwiGLU: act = h[:, :M] * silu(h[:, M:]) --------------------
// output tf32-rounded (feeds out GEMM)
__global__ void silu_kernel(const float* __restrict__ hb, float* __restrict__ act)
{
    const size_t idx = (size_t)blockIdx.x * 256 + threadIdx.x;   // float4 units
    const size_t r = idx >> 10;              // M/4 = 1024 float4 per row
    const int    j = (int)((idx & 1023) << 2);
    const float4 a = *(const float4*)(hb + r * (2 * M) + j);
    const float4 z = *(const float4*)(hb + r * (2 * M) + M + j);
    float4 o;
    o.x = rtf(a.x * z.x / (1.f + __expf(-z.x)));
    o.y = rtf(a.y * z.y / (1.f + __expf(-z.y)));
    o.z = rtf(a.z * z.z / (1.f + __expf(-z.z)));
    o.w = rtf(a.w * z.w / (1.f + __expf(-z.w)));
    *(float4*)(act + r * M + j) = o;
}

// ---------------- launch ------------------------------------------------------
extern "C" void kernel_launch(void* const* d_in, const int* in_sizes, int n_in,
                              void* d_out, int out_size)
{
    const float* x       = (const float*)d_in[0];
    const float* emb     = (const float*)d_in[1];
    const float* ln1_w   = (const float*)d_in[2];
    const float* ln1_lW  = (const float*)d_in[3];
    const float* ln1_lb  = (const float*)d_in[4];
    const float* ln2_w   = (const float*)d_in[5];
    const float* ln2_lW  = (const float*)d_in[6];
    const float* ln2_lb  = (const float*)d_in[7];
    const float* qkv_W   = (const float*)d_in[8];
    const float* qkv_b   = (const float*)d_in[9];
    const float* proj_W  = (const float*)d_in[10];
    const float* proj_b  = (const float*)d_in[11];
    const float* nq_w    = (const float*)d_in[12];
    const float* nk_w    = (const float*)d_in[13];
    const float* mlp_W   = (const float*)d_in[14];
    const float* mlp_b   = (const float*)d_in[15];
    const float* out_W   = (const float*)d_in[16];
    const float* out_b   = (const float*)d_in[17];
    const float* gates_W = (const float*)d_in[18];
    const float* gates_b = (const float*)d_in[19];
    float* outp = (float*)d_out;

    float *xn, *qkv, *ao, *xmid, *hb, *act, *wt, *ss1, *ss2, *gates;
    cudaGetSymbolAddress((void**)&xn,    g_xn);
    cudaGetSymbolAddress((void**)&qkv,   g_qkv);
    cudaGetSymbolAddress((void**)&ao,    g_ao);
    cudaGetSymbolAddress((void**)&xmid,  g_xmid);
    cudaGetSymbolAddress((void**)&hb,    g_h);
    cudaGetSymbolAddress((void**)&act,   g_act);
    cudaGetSymbolAddress((void**)&wt,    g_wt);
    cudaGetSymbolAddress((void**)&ss1,   g_ss1);
    cudaGetSymbolAddress((void**)&ss2,   g_ss2);
    cudaGetSymbolAddress((void**)&gates, g_gates);

    // tf32-rounded weight copies (carved from g_wt)
    float* wq = wt;                               // 1024*3072
    float* wp = wq + (size_t)D * 3 * D;           // 1024*1024
    float* wm = wp + (size_t)D * D;               // 1024*8192
    float* wo = wm + (size_t)D * 2 * M;           // 4096*1024

    cvtw_kernel<<<(D * 3 * D / 4 + 255) / 256, 256>>>((const float4*)qkv_W,  (float4*)wq, D * 3 * D / 4);
    cvtw_kernel<<<(D * D / 4     + 255) / 256, 256>>>((const float4*)proj_W, (float4*)wp, D * D / 4);
    cvtw_kernel<<<(D * 2 * M / 4 + 255) / 256, 256>>>((const float4*)mlp_W,  (float4*)wm, D * 2 * M / 4);
    cvtw_kernel<<<(M * D / 4     + 255) / 256, 256>>>((const float4*)out_W,  (float4*)wo, M * D / 4);

    // gates / ss1 / ss2 (all emb @ [E, 2D] + bias)
    emb_gemm3_kernel<<<dim3(2 * D / 64, B, 3), 256>>>(emb,
        gates_W, gates_b, gates,
        ln1_lW,  ln1_lb,  ss1,
        ln2_lW,  ln2_lb,  ss2);

    // xn = adaLN(x, ss1)   (tf32-rounded)
    adaln_kernel<<<BS, 256>>>(x, ss1, ln1_w, xn);

    // qkv = xn @ qkv_W + qkv_b
    gemm2<0><<<dim3(3 * D / 128, BS / 128), 256>>>(
        xn, wq, qkv_b, qkv, D, D, 3 * D, 3 * D, nullptr, nullptr);

    // rope + head rmsnorm on q, k (in place, tf32-rounded)
    rope_rms_kernel<<<BS * 2 * H / 4, 128>>>(qkv, nq_w, nk_w);

    // fused attention -> ao (tf32-rounded)
    flash_kernel<<<dim3(S / 128, B * H), 256>>>(qkv, ao);

    // xmid = x + gate_mha * (ao @ proj_W + proj_b)
    gemm2<1><<<dim3(D / 128, BS / 128), 256>>>(
        ao, wp, proj_b, xmid, D, D, D, D, x, gates);

    // xn2 = adaLN(xmid, ss2)  (tf32-rounded)
    adaln_kernel<<<BS, 256>>>(xmid, ss2, ln2_w, xn);

    // h = xn2 @ mlp_W + mlp_b
    gemm2<0><<<dim3(2 * M / 128, BS / 128), 256>>>(
        xn, wm, mlp_b, hb, D, D, 2 * M, 2 * M, nullptr, nullptr);

    // act = h[:, :M] * silu(h[:, M:])  (tf32-rounded)
    silu_kernel<<<(int)((size_t)BS * M / 4 / 256), 256>>>(hb, act);

    // out = xmid + gate_mlp * (act @ out_W + out_b)
    gemm2<1><<<dim3(D / 128, BS / 128), 256>>>(
        act, wo, out_b, outp, M, M, D, D, xmid, gates + D);
}